// round 9
// baseline (speedup 1.0000x reference)
#include <cuda_runtime.h>
#include <cuda_fp16.h>
#include <stdint.h>

#define NN 8192
#define DH 64
#define KC 64              // j's per chunk
#define KSPLIT 2
#define KHALF (NN / KSPLIT)
#define NCH (KHALF / KC)   // 64 chunks
#define TPB 256
#define TILE_I 64
// smem: W tile 64x64 fp16 (8KB) x2, B tile 64x64 fp16 (8KB) x2
#define WOFF0 0
#define WOFF1 8192
#define BOFF0 16384
#define BOFF1 24576
#define SMEM_BYTES 32768

// ---------------- device scratch ----------------
__device__ unsigned short g_adjp[NN * 512];    // packed adjacency bits (8MB)
__device__ unsigned short g_WhT[DH * NN];      // Wh^T fp16 [64][8192]
__device__ uint2 g_iAC[NN];                    // {half2(exp(src)), half2(exp(.2src))}
__device__ unsigned short g_jB[NN];            // half exp(dst)
__device__ unsigned short g_jD[NN];            // half exp(.2 dst)
__device__ float g_part[KSPLIT * NN * DH];     // K-split partial numerators
__device__ float g_den[KSPLIT * NN];           // K-split partial denominators

// ---------------- helpers ----------------
__device__ __forceinline__ uint32_t smem_u32(const void* p) {
    uint32_t a;
    asm("{ .reg .u64 t; cvta.to.shared.u64 t, %1; cvt.u32.u64 %0, t; }" : "=r"(a) : "l"(p));
    return a;
}
#define SWZ(off) ((off) ^ (((off) >> 3) & 0x70))

#define CPA16(d, s) asm volatile("cp.async.cg.shared.global [%0], [%1], 16;" :: "r"(d), "l"(s))
#define CPA_COMMIT() asm volatile("cp.async.commit_group;" ::: "memory")
#define CPA_WAIT0()  asm volatile("cp.async.wait_group 0;" ::: "memory")

__device__ __forceinline__ void ldsm_x4(uint32_t& r0, uint32_t& r1, uint32_t& r2, uint32_t& r3,
                                        uint32_t a) {
    asm volatile("ldmatrix.sync.aligned.m8n8.x4.shared.b16 {%0,%1,%2,%3}, [%4];"
                 : "=r"(r0), "=r"(r1), "=r"(r2), "=r"(r3) : "r"(a));
}
__device__ __forceinline__ void mma16816(float* d, const uint32_t* a, const uint32_t* b) {
    asm volatile("mma.sync.aligned.m16n8k16.row.col.f32.f16.f16.f32 "
                 "{%0,%1,%2,%3}, {%4,%5,%6,%7}, {%8,%9}, {%0,%1,%2,%3};"
                 : "+f"(d[0]), "+f"(d[1]), "+f"(d[2]), "+f"(d[3])
                 : "r"(a[0]), "r"(a[1]), "r"(a[2]), "r"(a[3]), "r"(b[0]), "r"(b[1]));
}

// ---------------- pack adjacency to bits (pure DRAM streaming) ----------------
// One CTA per row. bit k of g_adjp[row*512 + jj] <-> adj[row][jj*16+k].
__global__ void __launch_bounds__(256) pack_kernel(const int* __restrict__ adj) {
    int row = blockIdx.x, t = threadIdx.x, w = t >> 5, lane = t & 31;
    const int* r = adj + (size_t)row * NN;
    unsigned* dst = (unsigned*)(g_adjp + (size_t)row * 512);
#pragma unroll 8
    for (int k = 0; k < 32; k++) {
        int v = __ldcs(r + k * 256 + t);
        unsigned m = __ballot_sync(0xffffffffu, v != 0);
        if (lane == 0) dst[k * 8 + w] = m;
    }
}

// ---------------- prep: Wh^T fp16 + exp factors (fused combine for layer 1) ----------------
__global__ void __launch_bounds__(256) prep_kernel(const float* __restrict__ xa,
                                                   const float* __restrict__ xb,
                                                   const float* __restrict__ Wm,
                                                   const float* __restrict__ bv,
                                                   const float* __restrict__ av, int use_gx) {
    __shared__ float Ws[DH * DH];
    __shared__ float as_[2 * DH];
    __shared__ float bs[DH];
    int t = threadIdx.x;
    for (int k = t; k < DH * DH; k += 256) Ws[k] = Wm[k];
    if (t < 2 * DH) as_[t] = av[t];
    if (t < DH) bs[t] = bv[t];
    __syncthreads();

    int row_loc = t >> 2, q = t & 3;
    int row = blockIdx.x * 64 + row_loc;

    float x[DH];
    if (use_gx) {
        const float* p0 = g_part + (size_t)row * DH;
        const float* p1 = g_part + (size_t)NN * DH + (size_t)row * DH;
        float inv = 1.0f / (g_den[row] + g_den[NN + row]);
#pragma unroll
        for (int j = 0; j < 16; j++) {
            float4 v0 = ((const float4*)p0)[j];
            float4 v1 = ((const float4*)p1)[j];
            x[4 * j]     = fmaxf((v0.x + v1.x) * inv, 0.f);
            x[4 * j + 1] = fmaxf((v0.y + v1.y) * inv, 0.f);
            x[4 * j + 2] = fmaxf((v0.z + v1.z) * inv, 0.f);
            x[4 * j + 3] = fmaxf((v0.w + v1.w) * inv, 0.f);
        }
    } else {
        const float* xr = row < NN / 2 ? xa + (size_t)row * DH
                                       : xb + (size_t)(row - NN / 2) * DH;
#pragma unroll
        for (int j = 0; j < 16; j++) {
            float4 v = ((const float4*)xr)[j];
            x[4 * j] = v.x; x[4 * j + 1] = v.y; x[4 * j + 2] = v.z; x[4 * j + 3] = v.w;
        }
    }

    float srcv = 0.f, dstv = 0.f;
#pragma unroll
    for (int ii = 0; ii < 16; ii++) {
        int i = q * 16 + ii;
        const float4* w4 = (const float4*)(Ws + i * DH);
        float a0 = 0.f, a1 = 0.f, a2 = 0.f, a3 = 0.f;
#pragma unroll
        for (int p = 0; p < 16; p += 4) {
            float4 w;
            w = w4[p];     a0 = fmaf(x[4*p+3], w.w, fmaf(x[4*p+2], w.z, fmaf(x[4*p+1], w.y, fmaf(x[4*p], w.x, a0))));
            w = w4[p + 1]; a1 = fmaf(x[4*p+7], w.w, fmaf(x[4*p+6], w.z, fmaf(x[4*p+5], w.y, fmaf(x[4*p+4], w.x, a1))));
            w = w4[p + 2]; a2 = fmaf(x[4*p+11], w.w, fmaf(x[4*p+10], w.z, fmaf(x[4*p+9], w.y, fmaf(x[4*p+8], w.x, a2))));
            w = w4[p + 3]; a3 = fmaf(x[4*p+15], w.w, fmaf(x[4*p+14], w.z, fmaf(x[4*p+13], w.y, fmaf(x[4*p+12], w.x, a3))));
        }
        float wh = bs[i] + ((a0 + a1) + (a2 + a3));
        srcv = fmaf(wh, as_[i], srcv);
        dstv = fmaf(wh, as_[DH + i], dstv);
        g_WhT[(size_t)i * NN + row] = __half_as_ushort(__float2half_rn(wh));
    }
    srcv += __shfl_xor_sync(0xffffffffu, srcv, 1);
    srcv += __shfl_xor_sync(0xffffffffu, srcv, 2);
    dstv += __shfl_xor_sync(0xffffffffu, dstv, 1);
    dstv += __shfl_xor_sync(0xffffffffu, dstv, 2);
    if (q == 0) {
        __half2 Ah = __float2half2_rn(expf(srcv));
        __half2 Ch = __float2half2_rn(expf(0.2f * srcv));
        g_iAC[row] = make_uint2(*(uint32_t*)&Ah, *(uint32_t*)&Ch);
        g_jB[row] = __half_as_ushort(__float2half_rn(expf(dstv)));
        g_jD[row] = __half_as_ushort(__float2half_rn(expf(0.2f * dstv)));
    }
}

// ---------------- gen one chunk: 16 j's per thread (half2), from packed bits ----------------
__device__ __forceinline__ void gen_chunk(char* smemp, uint32_t wo,
                                          uint32_t wdst0, uint32_t wdst1,
                                          uint32_t A2, uint32_t C2,
                                          const uint4* pBc, const uint4* pDc,
                                          uint32_t bits, float& dsum) {
    __half2 A2h = *(__half2*)&A2, C2h = *(__half2*)&C2;
    uint4 Bq0 = pBc[0], Bq1 = pBc[1], Dq0 = pDc[0], Dq1 = pDc[1];
    uint32_t Bw[8] = {Bq0.x, Bq0.y, Bq0.z, Bq0.w, Bq1.x, Bq1.y, Bq1.z, Bq1.w};
    uint32_t Dw[8] = {Dq0.x, Dq0.y, Dq0.z, Dq0.w, Dq1.x, Dq1.y, Dq1.z, Dq1.w};
    uint32_t wv[8];
#pragma unroll
    for (int p = 0; p < 8; p++) {
        __half2 ab = __hmul2(A2h, *(__half2*)&Bw[p]);
        __half2 cd = __hmul2(C2h, *(__half2*)&Dw[p]);
        __half2 w = __hmax2(ab, cd);      // exp(leaky_relu(src+dst)) — exp monotone
        uint32_t e = (bits >> (2 * p)) & 3u;
        uint32_t m = ((e * 0x8001u) & 0x10001u) * 0xFFFFu;
        wv[p] = (*(uint32_t*)&w) & m;
    }
    __half2 s01 = __hadd2(*(__half2*)&wv[0], *(__half2*)&wv[1]);
    __half2 s23 = __hadd2(*(__half2*)&wv[2], *(__half2*)&wv[3]);
    __half2 s45 = __hadd2(*(__half2*)&wv[4], *(__half2*)&wv[5]);
    __half2 s67 = __hadd2(*(__half2*)&wv[6], *(__half2*)&wv[7]);
    float2 f0 = __half22float2(__hadd2(s01, s23));
    float2 f1 = __half22float2(__hadd2(s45, s67));
    dsum += (f0.x + f0.y) + (f1.x + f1.y);

    *(uint4*)(smemp + wo + wdst0) = make_uint4(wv[0], wv[1], wv[2], wv[3]);
    *(uint4*)(smemp + wo + wdst1) = make_uint4(wv[4], wv[5], wv[6], wv[7]);
}

// ---------------- attn: homogeneous HMMA flash-GAT, 64x4096 per CTA ----------------
__global__ void __launch_bounds__(TPB, 3) attn_mma() {
    extern __shared__ char smem[];
    uint32_t sb = smem_u32(smem);
    int t = threadIdx.x, wid = t >> 5, lane = t & 31;
    int tile = blockIdx.x >> 1, ks = blockIdx.x & 1;
    int i0 = tile * TILE_I, jbase = ks * KHALF;

    // ---- gen mapping: thread -> row i_loc, 16 j's at quarter jq16 ----
    int i_loc = t >> 2, jq16 = t & 3;
    int irow = i0 + i_loc;
    uint2 ac = g_iAC[irow];
    uint32_t wdst0 = SWZ((uint32_t)(i_loc * 128 + jq16 * 32));
    uint32_t wdst1 = SWZ((uint32_t)(i_loc * 128 + jq16 * 32 + 16));
    const uint4* pB = (const uint4*)(g_jB + jbase) + jq16 * 2;   // +c*8
    const uint4* pD = (const uint4*)(g_jD + jbase) + jq16 * 2;
    const unsigned short* pPack = g_adjp + (size_t)irow * 512 + (jbase >> 4) + jq16;  // +c*4
    float dsum = 0.f;

    // ---- B staging (cp.async): 512 16B segs = 2/thread ----
    int s0 = t, s1 = t + 256;
    uint32_t bd0 = SWZ((uint32_t)((s0 >> 3) * 128 + (s0 & 7) * 16));
    uint32_t bd1 = SWZ((uint32_t)((s1 >> 3) * 128 + (s1 & 7) * 16));
    const unsigned short* bs0p = g_WhT + (size_t)(s0 >> 3) * NN + jbase + (s0 & 7) * 8;
    const unsigned short* bs1p = g_WhT + (size_t)(s1 >> 3) * NN + jbase + (s1 & 7) * 8;

    // ---- GEMM mapping: 8 warps = 4 M-tiles(16) x 2 N-halves(32) ----
    int wm = wid & 3, wn = wid >> 2;
    int lr = lane & 7, lsel = lane >> 3;
    float acc[4][4];
#pragma unroll
    for (int n = 0; n < 4; n++)
#pragma unroll
        for (int p = 0; p < 4; p++) acc[n][p] = 0.f;

    // ---- stage chunk 0 ----
    uint32_t bits = pPack[0];
    CPA16(sb + BOFF0 + bd0, bs0p);
    CPA16(sb + BOFF0 + bd1, bs1p);
    CPA_COMMIT();
    gen_chunk(smem, WOFF0, wdst0, wdst1, ac.x, ac.y, pB, pD, bits, dsum);
    bits = pPack[4];
    CPA_WAIT0();
    __syncthreads();

    for (int c = 0; c < NCH; c++) {
        int buf = c & 1;
        if (c + 1 < NCH) {
            int nb = buf ^ 1;
            uint32_t bo = nb ? BOFF1 : BOFF0, wo = nb ? WOFF1 : WOFF0;
            CPA16(sb + bo + bd0, bs0p + (c + 1) * 64);
            CPA16(sb + bo + bd1, bs1p + (c + 1) * 64);
            CPA_COMMIT();
            gen_chunk(smem, wo, wdst0, wdst1, ac.x, ac.y,
                      pB + (size_t)(c + 1) * 8, pD + (size_t)(c + 1) * 8, bits, dsum);
            if (c + 2 < NCH) bits = pPack[(c + 2) * 4];
        }

        // ---- GEMM on chunk c ----
        uint32_t wbase = sb + (buf ? WOFF1 : WOFF0);
        uint32_t bbase = sb + (buf ? BOFF1 : BOFF0);
#pragma unroll
        for (int k = 0; k < 4; k++) {
            uint32_t af[4], bf[8];
            uint32_t a_adr = wbase + SWZ((uint32_t)((wm * 16 + lr + (lsel & 1) * 8) * 128 + ((lsel >> 1) * 8 + k * 16) * 2));
            ldsm_x4(af[0], af[1], af[2], af[3], a_adr);
#pragma unroll
            for (int p = 0; p < 2; p++) {
                uint32_t b_adr = bbase + SWZ((uint32_t)((wn * 32 + p * 16 + lr + (lsel >> 1) * 8) * 128 + ((lsel & 1) * 8 + k * 16) * 2));
                ldsm_x4(bf[p * 4 + 0], bf[p * 4 + 1], bf[p * 4 + 2], bf[p * 4 + 3], b_adr);
            }
            mma16816(acc[0], af, bf + 0);
            mma16816(acc[1], af, bf + 2);
            mma16816(acc[2], af, bf + 4);
            mma16816(acc[3], af, bf + 6);
        }
        CPA_WAIT0();
        __syncthreads();
    }

    // ---- denominator: reduce over the 4 gen threads of each row ----
    dsum += __shfl_xor_sync(0xffffffffu, dsum, 1);
    dsum += __shfl_xor_sync(0xffffffffu, dsum, 2);
    if (jq16 == 0) g_den[(size_t)ks * NN + irow] = dsum;

    // ---- epilogue: write partial numerators ----
    int row0 = i0 + wm * 16 + (lane >> 2);
    float* base = g_part + (size_t)ks * NN * DH;
#pragma unroll
    for (int nt = 0; nt < 4; nt++) {
        int col = wn * 32 + nt * 8 + (lane & 3) * 2;
        *(float2*)(base + (size_t)row0 * DH + col) = make_float2(acc[nt][0], acc[nt][1]);
        *(float2*)(base + (size_t)(row0 + 8) * DH + col) = make_float2(acc[nt][2], acc[nt][3]);
    }
}

// ---------------- final: fused combine + out = x @ out_w^T + out_b ----------------
__global__ void __launch_bounds__(256) final_kernel(const float* __restrict__ Wm,
                                                    const float* __restrict__ bv,
                                                    float* __restrict__ out) {
    __shared__ float Ws[DH * DH];
    __shared__ float bs[DH];
    int t = threadIdx.x;
    for (int k = t; k < DH * DH; k += 256) Ws[k] = Wm[k];
    if (t < DH) bs[t] = bv[t];
    __syncthreads();

    int row_loc = t >> 2, q = t & 3;
    int row = blockIdx.x * 64 + row_loc;

    const float* p0 = g_part + (size_t)row * DH;
    const float* p1 = g_part + (size_t)NN * DH + (size_t)row * DH;
    float inv = 1.0f / (g_den[row] + g_den[NN + row]);
    float x[DH];
#pragma unroll
    for (int j = 0; j < 16; j++) {
        float4 v0 = ((const float4*)p0)[j];
        float4 v1 = ((const float4*)p1)[j];
        x[4 * j]     = fmaxf((v0.x + v1.x) * inv, 0.f);
        x[4 * j + 1] = fmaxf((v0.y + v1.y) * inv, 0.f);
        x[4 * j + 2] = fmaxf((v0.z + v1.z) * inv, 0.f);
        x[4 * j + 3] = fmaxf((v0.w + v1.w) * inv, 0.f);
    }

    float res[16];
#pragma unroll
    for (int ii = 0; ii < 16; ii++) {
        int i = q * 16 + ii;
        const float4* w4 = (const float4*)(Ws + i * DH);
        float a0 = 0.f, a1 = 0.f, a2 = 0.f, a3 = 0.f;
#pragma unroll
        for (int p = 0; p < 16; p += 4) {
            float4 w;
            w = w4[p];     a0 = fmaf(x[4*p+3], w.w, fmaf(x[4*p+2], w.z, fmaf(x[4*p+1], w.y, fmaf(x[4*p], w.x, a0))));
            w = w4[p + 1]; a1 = fmaf(x[4*p+7], w.w, fmaf(x[4*p+6], w.z, fmaf(x[4*p+5], w.y, fmaf(x[4*p+4], w.x, a1))));
            w = w4[p + 2]; a2 = fmaf(x[4*p+11], w.w, fmaf(x[4*p+10], w.z, fmaf(x[4*p+9], w.y, fmaf(x[4*p+8], w.x, a2))));
            w = w4[p + 3]; a3 = fmaf(x[4*p+15], w.w, fmaf(x[4*p+14], w.z, fmaf(x[4*p+13], w.y, fmaf(x[4*p+12], w.x, a3))));
        }
        res[ii] = bs[i] + ((a0 + a1) + (a2 + a3));
    }
    float* orow = out + (size_t)row * DH + q * 16;
#pragma unroll
    for (int j = 0; j < 4; j++)
        ((float4*)orow)[j] = make_float4(res[4 * j], res[4 * j + 1], res[4 * j + 2], res[4 * j + 3]);
}

// ---------------- launch ----------------
extern "C" void kernel_launch(void* const* d_in, const int* in_sizes, int n_in,
                              void* d_out, int out_size) {
    const int*   adj  = (const int*)d_in[0];
    const float* user = (const float*)d_in[1];
    const float* item = (const float*)d_in[2];
    const float* W0   = (const float*)d_in[3];
    const float* b0   = (const float*)d_in[4];
    const float* a0   = (const float*)d_in[5];
    const float* W1   = (const float*)d_in[6];
    const float* b1   = (const float*)d_in[7];
    const float* a1   = (const float*)d_in[8];
    const float* ow   = (const float*)d_in[9];
    const float* ob   = (const float*)d_in[10];

    cudaFuncSetAttribute(attn_mma, cudaFuncAttributeMaxDynamicSharedMemorySize, SMEM_BYTES);

    pack_kernel<<<NN, 256>>>(adj);                                   // DRAM-bound streaming pack
    prep_kernel<<<NN / 64, 256>>>(user, item, W0, b0, a0, 0);
    attn_mma<<<(NN / TILE_I) * KSPLIT, TPB, SMEM_BYTES>>>();         // bits from L2
    prep_kernel<<<NN / 64, 256>>>(nullptr, nullptr, W1, b1, a1, 1);  // fused combine
    attn_mma<<<(NN / TILE_I) * KSPLIT, TPB, SMEM_BYTES>>>();         // bits from L2
    final_kernel<<<NN / 64, 256>>>(ow, ob, (float*)d_out);           // fused combine
}

// round 10
// speedup vs baseline: 1.1208x; 1.1208x over previous
#include <cuda_runtime.h>
#include <cuda_fp16.h>
#include <stdint.h>

#define NN 8192
#define DH 64
#define KC 64              // j's per chunk
#define KSPLIT 2
#define KHALF (NN / KSPLIT)
#define NCH (KHALF / KC)   // 64 chunks
#define TPB 256
#define TILE_I 64
#define PREPB 256          // prep CTAs in fused kernel (32 rows each)
#define PACKB 1024         // pack CTAs in fused kernel (8 adj rows each)
// smem: W tile 64x64 fp16 (8KB) x2, B tile 64x64 fp16 (8KB) x2
#define WOFF0 0
#define WOFF1 8192
#define BOFF0 16384
#define BOFF1 24576
#define SMEM_BYTES 32768

// ---------------- device scratch ----------------
__device__ unsigned short g_adjp[NN * 512];    // packed adjacency bits (8MB)
__device__ unsigned short g_WhT[DH * NN];      // Wh^T fp16 [64][8192]
__device__ uint2 g_iAC[NN];                    // {half2(exp(src)), half2(exp(.2src))}
__device__ unsigned short g_jB[NN];            // half exp(dst)
__device__ unsigned short g_jD[NN];            // half exp(.2 dst)
__device__ float g_part[KSPLIT * NN * DH];     // K-split partial numerators
__device__ float g_den[KSPLIT * NN];           // K-split partial denominators

// ---------------- helpers ----------------
__device__ __forceinline__ uint32_t smem_u32(const void* p) {
    uint32_t a;
    asm("{ .reg .u64 t; cvta.to.shared.u64 t, %1; cvt.u32.u64 %0, t; }" : "=r"(a) : "l"(p));
    return a;
}
#define SWZ(off) ((off) ^ (((off) >> 3) & 0x70))

#define CPA16(d, s) asm volatile("cp.async.cg.shared.global [%0], [%1], 16;" :: "r"(d), "l"(s))
#define CPA_COMMIT() asm volatile("cp.async.commit_group;" ::: "memory")
#define CPA_WAIT0()  asm volatile("cp.async.wait_group 0;" ::: "memory")

__device__ __forceinline__ void ldsm_x4(uint32_t& r0, uint32_t& r1, uint32_t& r2, uint32_t& r3,
                                        uint32_t a) {
    asm volatile("ldmatrix.sync.aligned.m8n8.x4.shared.b16 {%0,%1,%2,%3}, [%4];"
                 : "=r"(r0), "=r"(r1), "=r"(r2), "=r"(r3) : "r"(a));
}
__device__ __forceinline__ void mma16816(float* d, const uint32_t* a, const uint32_t* b) {
    asm volatile("mma.sync.aligned.m16n8k16.row.col.f32.f16.f16.f32 "
                 "{%0,%1,%2,%3}, {%4,%5,%6,%7}, {%8,%9}, {%0,%1,%2,%3};"
                 : "+f"(d[0]), "+f"(d[1]), "+f"(d[2]), "+f"(d[3])
                 : "r"(a[0]), "r"(a[1]), "r"(a[2]), "r"(a[3]), "r"(b[0]), "r"(b[1]));
}

// ---------------- prep body: 32 rows/CTA x 8 threads/row ----------------
__device__ __forceinline__ void prep_body(const float* __restrict__ xa,
                                          const float* __restrict__ xb,
                                          const float* __restrict__ Wm,
                                          const float* __restrict__ bv,
                                          const float* __restrict__ av,
                                          int use_gx, int bid, int t,
                                          float* Ws, float* as_, float* bs) {
    for (int k = t; k < DH * DH; k += 256) Ws[k] = Wm[k];
    if (t < 2 * DH) as_[t] = av[t];
    if (t < DH) bs[t] = bv[t];
    __syncthreads();

    int row_loc = t >> 3, q = t & 7;
    int row = bid * 32 + row_loc;

    float x[DH];
    if (use_gx) {
        const float* p0 = g_part + (size_t)row * DH;
        const float* p1 = g_part + (size_t)NN * DH + (size_t)row * DH;
        float inv = 1.0f / (g_den[row] + g_den[NN + row]);
#pragma unroll
        for (int j = 0; j < 16; j++) {
            float4 v0 = ((const float4*)p0)[j];
            float4 v1 = ((const float4*)p1)[j];
            x[4 * j]     = fmaxf((v0.x + v1.x) * inv, 0.f);
            x[4 * j + 1] = fmaxf((v0.y + v1.y) * inv, 0.f);
            x[4 * j + 2] = fmaxf((v0.z + v1.z) * inv, 0.f);
            x[4 * j + 3] = fmaxf((v0.w + v1.w) * inv, 0.f);
        }
    } else {
        const float* xr = row < NN / 2 ? xa + (size_t)row * DH
                                       : xb + (size_t)(row - NN / 2) * DH;
#pragma unroll
        for (int j = 0; j < 16; j++) {
            float4 v = ((const float4*)xr)[j];
            x[4 * j] = v.x; x[4 * j + 1] = v.y; x[4 * j + 2] = v.z; x[4 * j + 3] = v.w;
        }
    }

    float srcv = 0.f, dstv = 0.f;
#pragma unroll
    for (int ii = 0; ii < 8; ii++) {
        int i = q * 8 + ii;
        const float4* w4 = (const float4*)(Ws + i * DH);
        float a0 = 0.f, a1 = 0.f, a2 = 0.f, a3 = 0.f;
#pragma unroll
        for (int p = 0; p < 16; p += 4) {
            float4 w;
            w = w4[p];     a0 = fmaf(x[4*p+3], w.w, fmaf(x[4*p+2], w.z, fmaf(x[4*p+1], w.y, fmaf(x[4*p], w.x, a0))));
            w = w4[p + 1]; a1 = fmaf(x[4*p+7], w.w, fmaf(x[4*p+6], w.z, fmaf(x[4*p+5], w.y, fmaf(x[4*p+4], w.x, a1))));
            w = w4[p + 2]; a2 = fmaf(x[4*p+11], w.w, fmaf(x[4*p+10], w.z, fmaf(x[4*p+9], w.y, fmaf(x[4*p+8], w.x, a2))));
            w = w4[p + 3]; a3 = fmaf(x[4*p+15], w.w, fmaf(x[4*p+14], w.z, fmaf(x[4*p+13], w.y, fmaf(x[4*p+12], w.x, a3))));
        }
        float wh = bs[i] + ((a0 + a1) + (a2 + a3));
        srcv = fmaf(wh, as_[i], srcv);
        dstv = fmaf(wh, as_[DH + i], dstv);
        g_WhT[(size_t)i * NN + row] = __half_as_ushort(__float2half_rn(wh));
    }
    srcv += __shfl_xor_sync(0xffffffffu, srcv, 1);
    srcv += __shfl_xor_sync(0xffffffffu, srcv, 2);
    srcv += __shfl_xor_sync(0xffffffffu, srcv, 4);
    dstv += __shfl_xor_sync(0xffffffffu, dstv, 1);
    dstv += __shfl_xor_sync(0xffffffffu, dstv, 2);
    dstv += __shfl_xor_sync(0xffffffffu, dstv, 4);
    if (q == 0) {
        __half2 Ah = __float2half2_rn(expf(srcv));
        __half2 Ch = __float2half2_rn(expf(0.2f * srcv));
        g_iAC[row] = make_uint2(*(uint32_t*)&Ah, *(uint32_t*)&Ch);
        g_jB[row] = __half_as_ushort(__float2half_rn(expf(dstv)));
        g_jD[row] = __half_as_ushort(__float2half_rn(expf(0.2f * dstv)));
    }
}

// ---------------- fused pack (int4 streaming) + prep layer 0 ----------------
// blocks [0, PREPB): prep. blocks [PREPB, PREPB+PACKB): pack 8 adj rows each.
__global__ void __launch_bounds__(256) pack_prep0(const int* __restrict__ adj,
                                                  const float* __restrict__ user,
                                                  const float* __restrict__ item,
                                                  const float* __restrict__ Wm,
                                                  const float* __restrict__ bv,
                                                  const float* __restrict__ av) {
    __shared__ float Ws[DH * DH];
    __shared__ float as_[2 * DH];
    __shared__ float bs[DH];
    __shared__ uint8_t nib[8][256];
    int t = threadIdx.x;

    if (blockIdx.x < PREPB) {
        prep_body(user, item, Wm, bv, av, 0, blockIdx.x, t, Ws, as_, bs);
        return;
    }

    int pb = blockIdx.x - PREPB;
    int w = t >> 5, lane = t & 31;
    // block covers 16384 int4 (8 adj rows); warp covers 2048 int4.
    const int4* src = (const int4*)adj + (size_t)pb * 16384 + (size_t)w * 2048;
    uint32_t* dst = (uint32_t*)g_adjp + (size_t)pb * 2048 + (size_t)w * 256;

#pragma unroll 2
    for (int it = 0; it < 8; it++) {
        // coalesced: per r, warp reads 512B contiguous
        uint32_t mynib[8];
#pragma unroll
        for (int r = 0; r < 8; r++) {
            int4 v = __ldcs(src + it * 256 + r * 32 + lane);
            mynib[r] = (v.x != 0 ? 1u : 0u) | (v.y != 0 ? 2u : 0u) |
                       (v.z != 0 ? 4u : 0u) | (v.w != 0 ? 8u : 0u);
        }
#pragma unroll
        for (int r = 0; r < 8; r++) nib[w][r * 32 + lane] = (uint8_t)mynib[r];
        __syncwarp();
        // assemble: lane builds word `lane` of this iter from 8 nibble-bytes
        uint2 u = *(uint2*)&nib[w][(lane >> 2) * 32 + (lane & 3) * 8];
        uint32_t x0 = (u.x | (u.x >> 4)) & 0x00FF00FFu; x0 = (x0 | (x0 >> 8)) & 0xFFFFu;
        uint32_t x1 = (u.y | (u.y >> 4)) & 0x00FF00FFu; x1 = (x1 | (x1 >> 8)) & 0xFFFFu;
        dst[it * 32 + lane] = x0 | (x1 << 16);
        __syncwarp();
    }
}

// ---------------- standalone prep (layer 1, fused combine) ----------------
__global__ void __launch_bounds__(256) prep_kernel(const float* __restrict__ Wm,
                                                   const float* __restrict__ bv,
                                                   const float* __restrict__ av) {
    __shared__ float Ws[DH * DH];
    __shared__ float as_[2 * DH];
    __shared__ float bs[DH];
    prep_body(nullptr, nullptr, Wm, bv, av, 1, blockIdx.x, threadIdx.x, Ws, as_, bs);
}

// ---------------- gen one chunk: 16 j's per thread (half2), from packed bits ----------------
__device__ __forceinline__ void gen_chunk(char* smemp, uint32_t wo,
                                          uint32_t wdst0, uint32_t wdst1,
                                          uint32_t A2, uint32_t C2,
                                          const uint4* pBc, const uint4* pDc,
                                          uint32_t bits, float& dsum) {
    __half2 A2h = *(__half2*)&A2, C2h = *(__half2*)&C2;
    uint4 Bq0 = pBc[0], Bq1 = pBc[1], Dq0 = pDc[0], Dq1 = pDc[1];
    uint32_t Bw[8] = {Bq0.x, Bq0.y, Bq0.z, Bq0.w, Bq1.x, Bq1.y, Bq1.z, Bq1.w};
    uint32_t Dw[8] = {Dq0.x, Dq0.y, Dq0.z, Dq0.w, Dq1.x, Dq1.y, Dq1.z, Dq1.w};
    uint32_t wv[8];
#pragma unroll
    for (int p = 0; p < 8; p++) {
        __half2 ab = __hmul2(A2h, *(__half2*)&Bw[p]);
        __half2 cd = __hmul2(C2h, *(__half2*)&Dw[p]);
        __half2 w = __hmax2(ab, cd);      // exp(leaky_relu(src+dst)) — exp monotone
        uint32_t e = (bits >> (2 * p)) & 3u;
        uint32_t m = ((e * 0x8001u) & 0x10001u) * 0xFFFFu;
        wv[p] = (*(uint32_t*)&w) & m;
    }
    __half2 s01 = __hadd2(*(__half2*)&wv[0], *(__half2*)&wv[1]);
    __half2 s23 = __hadd2(*(__half2*)&wv[2], *(__half2*)&wv[3]);
    __half2 s45 = __hadd2(*(__half2*)&wv[4], *(__half2*)&wv[5]);
    __half2 s67 = __hadd2(*(__half2*)&wv[6], *(__half2*)&wv[7]);
    float2 f0 = __half22float2(__hadd2(s01, s23));
    float2 f1 = __half22float2(__hadd2(s45, s67));
    dsum += (f0.x + f0.y) + (f1.x + f1.y);

    *(uint4*)(smemp + wo + wdst0) = make_uint4(wv[0], wv[1], wv[2], wv[3]);
    *(uint4*)(smemp + wo + wdst1) = make_uint4(wv[4], wv[5], wv[6], wv[7]);
}

// ---------------- attn: homogeneous HMMA flash-GAT, 64x4096 per CTA ----------------
__global__ void __launch_bounds__(TPB, 2) attn_mma() {
    extern __shared__ char smem[];
    uint32_t sb = smem_u32(smem);
    int t = threadIdx.x, wid = t >> 5, lane = t & 31;
    int tile = blockIdx.x >> 1, ks = blockIdx.x & 1;
    int i0 = tile * TILE_I, jbase = ks * KHALF;

    // ---- gen mapping: thread -> row i_loc, 16 j's at quarter jq16 ----
    int i_loc = t >> 2, jq16 = t & 3;
    int irow = i0 + i_loc;
    uint2 ac = g_iAC[irow];
    uint32_t wdst0 = SWZ((uint32_t)(i_loc * 128 + jq16 * 32));
    uint32_t wdst1 = SWZ((uint32_t)(i_loc * 128 + jq16 * 32 + 16));
    const uint4* pB = (const uint4*)(g_jB + jbase) + jq16 * 2;   // +c*8
    const uint4* pD = (const uint4*)(g_jD + jbase) + jq16 * 2;
    const unsigned short* pPack = g_adjp + (size_t)irow * 512 + (jbase >> 4) + jq16;  // +c*4
    float dsum = 0.f;

    // ---- B staging (cp.async): 512 16B segs = 2/thread ----
    int s0 = t, s1 = t + 256;
    uint32_t bd0 = SWZ((uint32_t)((s0 >> 3) * 128 + (s0 & 7) * 16));
    uint32_t bd1 = SWZ((uint32_t)((s1 >> 3) * 128 + (s1 & 7) * 16));
    const unsigned short* bs0p = g_WhT + (size_t)(s0 >> 3) * NN + jbase + (s0 & 7) * 8;
    const unsigned short* bs1p = g_WhT + (size_t)(s1 >> 3) * NN + jbase + (s1 & 7) * 8;

    // ---- GEMM mapping: 8 warps = 4 M-tiles(16) x 2 N-halves(32) ----
    int wm = wid & 3, wn = wid >> 2;
    int lr = lane & 7, lsel = lane >> 3;
    float acc[4][4];
#pragma unroll
    for (int n = 0; n < 4; n++)
#pragma unroll
        for (int p = 0; p < 4; p++) acc[n][p] = 0.f;

    // ---- stage chunk 0 ----
    uint32_t bits = pPack[0];
    CPA16(sb + BOFF0 + bd0, bs0p);
    CPA16(sb + BOFF0 + bd1, bs1p);
    CPA_COMMIT();
    gen_chunk(smem, WOFF0, wdst0, wdst1, ac.x, ac.y, pB, pD, bits, dsum);
    bits = pPack[4];
    CPA_WAIT0();
    __syncthreads();

    for (int c = 0; c < NCH; c++) {
        int buf = c & 1;
        if (c + 1 < NCH) {
            int nb = buf ^ 1;
            uint32_t bo = nb ? BOFF1 : BOFF0, wo = nb ? WOFF1 : WOFF0;
            CPA16(sb + bo + bd0, bs0p + (c + 1) * 64);
            CPA16(sb + bo + bd1, bs1p + (c + 1) * 64);
            CPA_COMMIT();
            gen_chunk(smem, wo, wdst0, wdst1, ac.x, ac.y,
                      pB + (size_t)(c + 1) * 8, pD + (size_t)(c + 1) * 8, bits, dsum);
            if (c + 2 < NCH) bits = pPack[(c + 2) * 4];
        }

        // ---- GEMM on chunk c ----
        uint32_t wbase = sb + (buf ? WOFF1 : WOFF0);
        uint32_t bbase = sb + (buf ? BOFF1 : BOFF0);
#pragma unroll
        for (int k = 0; k < 4; k++) {
            uint32_t af[4], bf[8];
            uint32_t a_adr = wbase + SWZ((uint32_t)((wm * 16 + lr + (lsel & 1) * 8) * 128 + ((lsel >> 1) * 8 + k * 16) * 2));
            ldsm_x4(af[0], af[1], af[2], af[3], a_adr);
#pragma unroll
            for (int p = 0; p < 2; p++) {
                uint32_t b_adr = bbase + SWZ((uint32_t)((wn * 32 + p * 16 + lr + (lsel >> 1) * 8) * 128 + ((lsel & 1) * 8 + k * 16) * 2));
                ldsm_x4(bf[p * 4 + 0], bf[p * 4 + 1], bf[p * 4 + 2], bf[p * 4 + 3], b_adr);
            }
            mma16816(acc[0], af, bf + 0);
            mma16816(acc[1], af, bf + 2);
            mma16816(acc[2], af, bf + 4);
            mma16816(acc[3], af, bf + 6);
        }
        CPA_WAIT0();
        __syncthreads();
    }

    // ---- denominator: reduce over the 4 gen threads of each row ----
    dsum += __shfl_xor_sync(0xffffffffu, dsum, 1);
    dsum += __shfl_xor_sync(0xffffffffu, dsum, 2);
    if (jq16 == 0) g_den[(size_t)ks * NN + irow] = dsum;

    // ---- epilogue: write partial numerators ----
    int row0 = i0 + wm * 16 + (lane >> 2);
    float* base = g_part + (size_t)ks * NN * DH;
#pragma unroll
    for (int nt = 0; nt < 4; nt++) {
        int col = wn * 32 + nt * 8 + (lane & 3) * 2;
        *(float2*)(base + (size_t)row0 * DH + col) = make_float2(acc[nt][0], acc[nt][1]);
        *(float2*)(base + (size_t)(row0 + 8) * DH + col) = make_float2(acc[nt][2], acc[nt][3]);
    }
}

// ---------------- final: fused combine + out = x @ out_w^T + out_b ----------------
// 32 rows/CTA x 8 threads/row, grid 256.
__global__ void __launch_bounds__(256) final_kernel(const float* __restrict__ Wm,
                                                    const float* __restrict__ bv,
                                                    float* __restrict__ out) {
    __shared__ float Ws[DH * DH];
    __shared__ float bs[DH];
    int t = threadIdx.x;
    for (int k = t; k < DH * DH; k += 256) Ws[k] = Wm[k];
    if (t < DH) bs[t] = bv[t];
    __syncthreads();

    int row_loc = t >> 3, q = t & 7;
    int row = blockIdx.x * 32 + row_loc;

    const float* p0 = g_part + (size_t)row * DH;
    const float* p1 = g_part + (size_t)NN * DH + (size_t)row * DH;
    float inv = 1.0f / (g_den[row] + g_den[NN + row]);
    float x[DH];
#pragma unroll
    for (int j = 0; j < 16; j++) {
        float4 v0 = ((const float4*)p0)[j];
        float4 v1 = ((const float4*)p1)[j];
        x[4 * j]     = fmaxf((v0.x + v1.x) * inv, 0.f);
        x[4 * j + 1] = fmaxf((v0.y + v1.y) * inv, 0.f);
        x[4 * j + 2] = fmaxf((v0.z + v1.z) * inv, 0.f);
        x[4 * j + 3] = fmaxf((v0.w + v1.w) * inv, 0.f);
    }

    float res[8];
#pragma unroll
    for (int ii = 0; ii < 8; ii++) {
        int i = q * 8 + ii;
        const float4* w4 = (const float4*)(Ws + i * DH);
        float a0 = 0.f, a1 = 0.f, a2 = 0.f, a3 = 0.f;
#pragma unroll
        for (int p = 0; p < 16; p += 4) {
            float4 w;
            w = w4[p];     a0 = fmaf(x[4*p+3], w.w, fmaf(x[4*p+2], w.z, fmaf(x[4*p+1], w.y, fmaf(x[4*p], w.x, a0))));
            w = w4[p + 1]; a1 = fmaf(x[4*p+7], w.w, fmaf(x[4*p+6], w.z, fmaf(x[4*p+5], w.y, fmaf(x[4*p+4], w.x, a1))));
            w = w4[p + 2]; a2 = fmaf(x[4*p+11], w.w, fmaf(x[4*p+10], w.z, fmaf(x[4*p+9], w.y, fmaf(x[4*p+8], w.x, a2))));
            w = w4[p + 3]; a3 = fmaf(x[4*p+15], w.w, fmaf(x[4*p+14], w.z, fmaf(x[4*p+13], w.y, fmaf(x[4*p+12], w.x, a3))));
        }
        res[ii] = bs[i] + ((a0 + a1) + (a2 + a3));
    }
    float* orow = out + (size_t)row * DH + q * 8;
    ((float4*)orow)[0] = make_float4(res[0], res[1], res[2], res[3]);
    ((float4*)orow)[1] = make_float4(res[4], res[5], res[6], res[7]);
}

// ---------------- launch ----------------
extern "C" void kernel_launch(void* const* d_in, const int* in_sizes, int n_in,
                              void* d_out, int out_size) {
    const int*   adj  = (const int*)d_in[0];
    const float* user = (const float*)d_in[1];
    const float* item = (const float*)d_in[2];
    const float* W0   = (const float*)d_in[3];
    const float* b0   = (const float*)d_in[4];
    const float* a0   = (const float*)d_in[5];
    const float* W1   = (const float*)d_in[6];
    const float* b1   = (const float*)d_in[7];
    const float* a1   = (const float*)d_in[8];
    const float* ow   = (const float*)d_in[9];
    const float* ob   = (const float*)d_in[10];

    cudaFuncSetAttribute(attn_mma, cudaFuncAttributeMaxDynamicSharedMemorySize, SMEM_BYTES);

    pack_prep0<<<PREPB + PACKB, 256>>>(adj, user, item, W0, b0, a0);  // pack ∥ prep0
    attn_mma<<<(NN / TILE_I) * KSPLIT, TPB, SMEM_BYTES>>>();          // bits from L2
    prep_kernel<<<NN / 32, 256>>>(W1, b1, a1);                        // fused combine
    attn_mma<<<(NN / TILE_I) * KSPLIT, TPB, SMEM_BYTES>>>();          // bits from L2
    final_kernel<<<NN / 32, 256>>>(ow, ob, (float*)d_out);            // fused combine
}